// round 5
// baseline (speedup 1.0000x reference)
#include <cuda_runtime.h>
#include <cuda_bf16.h>
#include <cstdint>

#define BB 4
#define CC 128
#define CO 64
#define NN 4096
#define TQ 64
#define TMT 64
#define NSTEP (NN / TMT)

typedef unsigned long long ull;

// ---------------- scratch (device globals) ----------------------------------
__device__ __align__(16) __nv_bfloat16 KhG[BB * NN * CO];
__device__ __align__(16) __nv_bfloat16 KlG[BB * NN * CO];
__device__ __align__(16) __nv_bfloat16 VhG[BB * NN * CO];   // token-major [b][m][o]
__device__ __align__(16) __nv_bfloat16 VlG[BB * NN * CO];

// ---------------- helpers ----------------------------------------------------
__device__ __forceinline__ uint32_t smem_u32(const void* p) {
    uint32_t a;
    asm("{ .reg .u64 t; cvta.to.shared.u64 t, %1; cvt.u32.u64 %0, t; }"
        : "=r"(a) : "l"(p));
    return a;
}
__device__ __forceinline__ float ex2f(float x) {
    float y; asm("ex2.approx.f32 %0, %1;" : "=f"(y) : "f"(x)); return y;
}
#define SWZ128(off) ((off) ^ (((off) >> 3) & 0x70))

#define LDSM_X4(r0,r1,r2,r3,addr) \
    asm volatile("ldmatrix.sync.aligned.m8n8.x4.shared.b16 {%0,%1,%2,%3}, [%4];" \
        : "=r"(r0),"=r"(r1),"=r"(r2),"=r"(r3) : "r"(addr))
#define LDSM_X4T(r0,r1,r2,r3,addr) \
    asm volatile("ldmatrix.sync.aligned.m8n8.x4.trans.shared.b16 {%0,%1,%2,%3}, [%4];" \
        : "=r"(r0),"=r"(r1),"=r"(r2),"=r"(r3) : "r"(addr))

#define MMA16816(c0,c1,c2,c3,a0,a1,a2,a3,b0,b1) \
    asm volatile("mma.sync.aligned.m16n8k16.row.col.f32.bf16.bf16.f32 " \
        "{%0,%1,%2,%3}, {%4,%5,%6,%7}, {%8,%9}, {%0,%1,%2,%3};" \
        : "+f"(c0),"+f"(c1),"+f"(c2),"+f"(c3) \
        : "r"(a0),"r"(a1),"r"(a2),"r"(a3),"r"(b0),"r"(b1))

__device__ __forceinline__ void cpa16(uint32_t dst, const void* src) {
    asm volatile("cp.async.cg.shared.global [%0], [%1], 16;" :: "r"(dst), "l"(src));
}
#define CP_COMMIT() asm volatile("cp.async.commit_group;" ::: "memory")
#define CP_WAIT(n)  asm volatile("cp.async.wait_group %0;" :: "n"(n) : "memory")

__device__ __forceinline__ uint32_t pack_bf16(float lo, float hi) {
    uint32_t r;
    asm("cvt.rn.bf16x2.f32 %0, %1, %2;" : "=r"(r) : "f"(hi), "f"(lo));
    return r;
}
__device__ __forceinline__ ull packf2(float lo, float hi) {
    ull r; asm("mov.b64 %0, {%1, %2};" : "=l"(r) : "f"(lo), "f"(hi)); return r;
}
__device__ __forceinline__ void unpackf2(ull v, float& lo, float& hi) {
    asm("mov.b64 {%0, %1}, %2;" : "=f"(lo), "=f"(hi) : "l"(v));
}
__device__ __forceinline__ ull fma2(ull a, ull b, ull c) {
    ull d; asm("fma.rn.f32x2 %0, %1, %2, %3;" : "=l"(d) : "l"(a), "l"(b), "l"(c));
    return d;
}

// 64 rows x 64 bf16 (8KB) -> smem SW128, 128 threads, 4 cp.async each
__device__ __forceinline__ void load_arr64(uint32_t dst, const __nv_bfloat16* src, int tid) {
#pragma unroll
    for (int it = 0; it < 4; it++) {
        int i = tid + it * 128;
        int row = i >> 3, ch = i & 7;
        cpa16(dst + SWZ128((uint32_t)(row * 128 + ch * 16)),
              src + (size_t)row * CO + ch * 8);
    }
}

// ---------------------------------------------------------------------------
// K/V projection + split-bf16 store (unchanged from R4, nsets=2).
// ---------------------------------------------------------------------------
__global__ void __launch_bounds__(256) proj2_kernel(
    const float* __restrict__ x,
    const float* __restrict__ w0, const float* __restrict__ b0,
    __nv_bfloat16* __restrict__ hi0, __nv_bfloat16* __restrict__ lo0,
    const float* __restrict__ w1, const float* __restrict__ b1,
    __nv_bfloat16* __restrict__ hi1, __nv_bfloat16* __restrict__ lo1)
{
    extern __shared__ float sm[];
    float* Xs  = sm;                    // 8192
    float* Ws  = sm + 8192;             // 8192
    float* stgH = sm + 16384;           // 2048
    float* stgL = sm + 18432;           // 2048

    int b  = blockIdx.y;
    int n0 = blockIdx.x * 64;
    int tid = threadIdx.x;

    const float* xb = x + (size_t)b * CC * NN + n0;
    for (int i = tid; i < 2048; i += 256) {
        int c = i >> 4, j4 = (i & 15) * 4;
        *(float4*)&Xs[c * 64 + j4] = *(const float4*)&xb[(size_t)c * NN + j4];
    }

    int nx = (tid & 15) * 4;
    int og = tid >> 4;

    for (int s = 0; s < 2; s++) {
        const float* w   = s ? w1 : w0;
        const float* bia = s ? b1 : b0;
        __nv_bfloat16* hi = s ? hi1 : hi0;
        __nv_bfloat16* lo = s ? lo1 : lo0;

        __syncthreads();
        for (int i = tid; i < 2048; i += 256)
            *(float4*)&Ws[i * 4] = *(const float4*)&w[i * 4];
        __syncthreads();

        float acc[4][4];
#pragma unroll
        for (int i = 0; i < 4; i++)
#pragma unroll
            for (int j = 0; j < 4; j++) acc[i][j] = 0.f;

#pragma unroll 4
        for (int c = 0; c < CC; c += 2) {
            float4 xa = *(const float4*)&Xs[c * 64 + nx];
            float4 xb2 = *(const float4*)&Xs[(c + 1) * 64 + nx];
#pragma unroll
            for (int oi = 0; oi < 4; oi++) {
                float2 w2 = *(const float2*)&Ws[(og * 4 + oi) * CC + c];
                acc[oi][0] += w2.x * xa.x + w2.y * xb2.x;
                acc[oi][1] += w2.x * xa.y + w2.y * xb2.y;
                acc[oi][2] += w2.x * xa.z + w2.y * xb2.z;
                acc[oi][3] += w2.x * xa.w + w2.y * xb2.w;
            }
        }

        float bb[4];
#pragma unroll
        for (int oi = 0; oi < 4; oi++) bb[oi] = bia[og * 4 + oi];

#pragma unroll
        for (int j = 0; j < 4; j++) {
            float v0 = acc[0][j] + bb[0];
            float v1 = acc[1][j] + bb[1];
            float v2 = acc[2][j] + bb[2];
            float v3 = acc[3][j] + bb[3];
            uint32_t h01 = pack_bf16(v0, v1), h23 = pack_bf16(v2, v3);
            float l0 = v0 - __uint_as_float(h01 << 16);
            float l1 = v1 - __uint_as_float(h01 & 0xFFFF0000u);
            float l2 = v2 - __uint_as_float(h23 << 16);
            float l3 = v3 - __uint_as_float(h23 & 0xFFFF0000u);
            int fo = (nx + j) * 32 + og * 2;
            stgH[fo] = __uint_as_float(h01); stgH[fo + 1] = __uint_as_float(h23);
            uint32_t q01 = pack_bf16(l0, l1), q23 = pack_bf16(l2, l3);
            stgL[fo] = __uint_as_float(q01); stgL[fo + 1] = __uint_as_float(q23);
        }
        __syncthreads();

        uint4* dH = (uint4*)(hi + ((size_t)b * NN + n0) * CO);
        uint4* dL = (uint4*)(lo + ((size_t)b * NN + n0) * CO);
        for (int i = tid; i < 512; i += 256) {
            dH[i] = ((uint4*)stgH)[i];
            dL[i] = ((uint4*)stgL)[i];
        }
    }
}

// ---------------------------------------------------------------------------
// Fused kernel: Q-proj prologue + FA2 mainloop + conv/BN/ReLU/residual epilogue
// smem: S0 32KB | S1 32KB (double-buffer stages) | WCC 32KB (wqT fp32 ->
//       later wc hi/lo bf16)
// ---------------------------------------------------------------------------
#define S0 0
#define S1 32768
#define WCC 65536
#define STG_BYTES 32768
#define SMEM_ATTN 98304

__global__ void __launch_bounds__(128, 2) attn_fused_kernel(
    const float* __restrict__ range_x,
    const float* __restrict__ wq, const float* __restrict__ bq,
    const float* __restrict__ wc, const float* __restrict__ bc,
    const float* __restrict__ gam, const float* __restrict__ bet,
    const float* __restrict__ mea, const float* __restrict__ va,
    const float* __restrict__ img, float* __restrict__ out)
{
    extern __shared__ char smem[];
    const uint32_t sb = smem_u32(smem);

    int tid  = threadIdx.x;
    int lane = tid & 31;
    int wid  = tid >> 5;
    int b    = blockIdx.y;
    int n0   = blockIdx.x * TQ;
    int r0   = wid * 16;

    size_t kb = (size_t)b * NN * CO;
    const float LOG2E = 1.4426950408889634f;

    // ---- (a) async load r tile [128c][64n] fp32 -> S0, wq [64][128] -> S1 ----
    {
        const float* rX = range_x + (size_t)b * CC * NN + n0;
#pragma unroll
        for (int it = 0; it < 16; it++) {
            int i = tid + it * 128;
            int row = i >> 4, ch = i & 15;
            cpa16(sb + S0 + row * 256 + ch * 16, rX + (size_t)row * NN + ch * 4);
        }
#pragma unroll
        for (int it = 0; it < 16; it++) {
            int i = tid + it * 128;
            cpa16(sb + S1 + i * 16, wq + i * 4);
        }
    }
    CP_COMMIT(); CP_WAIT(0); __syncthreads();

    // ---- (b) transpose wq -> WCC fp32 [c][o] ----
    {
        float* WqT = (float*)(smem + WCC);
        const float* Wq = (const float*)(smem + S1);
#pragma unroll
        for (int it = 0; it < 16; it++) {
            int i = tid + it * 128;
            int o = i >> 5, c4 = (i & 31) * 4;
            float4 w = *(const float4*)&Wq[o * 128 + c4];
            WqT[(c4 + 0) * 64 + o] = w.x;
            WqT[(c4 + 1) * 64 + o] = w.y;
            WqT[(c4 + 2) * 64 + o] = w.z;
            WqT[(c4 + 3) * 64 + o] = w.w;
        }
    }
    __syncthreads();

    // ---- (c) async load wc fp32 -> S1 (overlaps q compute) ----
#pragma unroll
    for (int it = 0; it < 16; it++) {
        int i = tid + it * 128;
        cpa16(sb + S1 + i * 16, wc + i * 4);
    }
    CP_COMMIT();

    // ---- (d) q compute: thread -> (n = tid>>1, o0 = (tid&1)*32), 32 outputs --
    ull acc64[16];
    {
        int qn = tid >> 1, o0 = (tid & 1) * 32;
        const float* Rs  = (const float*)(smem + S0);
        const float* WqT = (const float*)(smem + WCC);
#pragma unroll
        for (int i = 0; i < 16; i++)
            acc64[i] = packf2(__ldg(bq + o0 + 2 * i), __ldg(bq + o0 + 2 * i + 1));
#pragma unroll 4
        for (int c = 0; c < CC; c++) {
            float rv = Rs[c * 64 + qn];
            ull rv2 = packf2(rv, rv);
            const ulonglong2* Wp = (const ulonglong2*)&WqT[c * 64 + o0];
#pragma unroll
            for (int j = 0; j < 8; j++) {
                ulonglong2 w2 = Wp[j];
                acc64[2 * j]     = fma2(w2.x, rv2, acc64[2 * j]);
                acc64[2 * j + 1] = fma2(w2.y, rv2, acc64[2 * j + 1]);
            }
        }
    }

    // ---- (e) wait wc; everyone done with S0 (r) / WCC (wqT) ----
    CP_WAIT(0); __syncthreads();

    // ---- (f) write q split -> S0 (hi), S0+8192 (lo); convert wc -> WCC ----
    {
        int qn = tid >> 1, o0 = (tid & 1) * 32;
#pragma unroll
        for (int i = 0; i < 16; i++) {
            float f0, f1;
            unpackf2(acc64[i], f0, f1);
            f0 *= LOG2E; f1 *= LOG2E;
            uint32_t h = pack_bf16(f0, f1);
            float l0 = f0 - __uint_as_float(h << 16);
            float l1 = f1 - __uint_as_float(h & 0xFFFF0000u);
            uint32_t off = SWZ128((uint32_t)(qn * 128 + (o0 + 2 * i) * 2));
            *(uint32_t*)(smem + S0 + off)        = h;
            *(uint32_t*)(smem + S0 + 8192 + off) = pack_bf16(l0, l1);
        }
        // wc: S1 fp32 [c][64 o] -> WCC hi (16KB) / lo (16KB) bf16, SW128
        const float* Wc = (const float*)(smem + S1);
#pragma unroll
        for (int it = 0; it < 16; it++) {
            int i = tid + it * 128;
            int c = i >> 4, o4 = (i & 15) * 4;
            float4 w = *(const float4*)&Wc[c * 64 + o4];
            uint32_t h01 = pack_bf16(w.x, w.y), h23 = pack_bf16(w.z, w.w);
            float l0 = w.x - __uint_as_float(h01 << 16);
            float l1 = w.y - __uint_as_float(h01 & 0xFFFF0000u);
            float l2 = w.z - __uint_as_float(h23 << 16);
            float l3 = w.w - __uint_as_float(h23 & 0xFFFF0000u);
            uint32_t off = SWZ128((uint32_t)(c * 128 + o4 * 2));
            *(uint32_t*)(smem + WCC + off)             = h01;
            *(uint32_t*)(smem + WCC + off + 4)         = h23;
            *(uint32_t*)(smem + WCC + 16384 + off)     = pack_bf16(l0, l1);
            *(uint32_t*)(smem + WCC + 16384 + off + 4) = pack_bf16(l2, l3);
        }
    }
    __syncthreads();

    // ---- (g) Q A-fragments ----
    uint32_t QH[4][4], QL[4][4];
    {
        int rq = r0 + (lane & 7) + ((lane >> 3) & 1) * 8;
        uint32_t cq = ((lane >> 4) & 1) * 16;
#pragma unroll
        for (int ks = 0; ks < 4; ks++) {
            uint32_t off = SWZ128((uint32_t)(rq * 128 + ks * 32 + cq));
            LDSM_X4(QH[ks][0], QH[ks][1], QH[ks][2], QH[ks][3], sb + S0 + off);
            LDSM_X4(QL[ks][0], QL[ks][1], QL[ks][2], QL[ks][3], sb + S0 + 8192 + off);
        }
    }
    __syncthreads();

    // ---- (h) prologue: tile 0 into S0 ----
    load_arr64(sb + 0,     KhG + kb, tid);
    load_arr64(sb + 8192,  KlG + kb, tid);
    load_arr64(sb + 16384, VhG + kb, tid);
    load_arr64(sb + 24576, VlG + kb, tid);
    CP_COMMIT();

    float Oa[8][4];
#pragma unroll
    for (int i = 0; i < 8; i++)
#pragma unroll
        for (int j = 0; j < 4; j++) Oa[i][j] = 0.f;
    float Lg = 0.f, Lg8 = 0.f;

    const int rowk = (lane & 7);
    const uint32_t cbk = ((uint32_t)(lane >> 3)) * 16;
    const int rv = (lane & 7) + ((lane >> 3) & 1) * 8;
    const uint32_t cbv = ((uint32_t)((lane >> 4) & 1)) * 16;

    for (int t = 0; t < NSTEP; t++) {
        if (t + 1 < NSTEP) {
            uint32_t db = sb + ((t + 1) & 1) * STG_BYTES;
            size_t gb = kb + (size_t)(t + 1) * TMT * CO;
            load_arr64(db + 0,     KhG + gb, tid);
            load_arr64(db + 8192,  KlG + gb, tid);
            load_arr64(db + 16384, VhG + gb, tid);
            load_arr64(db + 24576, VlG + gb, tid);
            CP_COMMIT();
            CP_WAIT(1);
        } else {
            CP_WAIT(0);
        }
        __syncthreads();

        const uint32_t kh_b = sb + (t & 1) * STG_BYTES;
        const uint32_t kl_b = kh_b + 8192;
        const uint32_t vh_b = kh_b + 16384;
        const uint32_t vl_b = kh_b + 24576;

#pragma unroll
        for (int mbp = 0; mbp < 4; mbp++) {
            uint32_t PH2[2][2], PL2[2][2];
#pragma unroll
            for (int half = 0; half < 2; half++) {
                int mb = mbp * 2 + half;
                float c0 = 0.f, c1 = 0.f, c2 = 0.f, c3 = 0.f;
#pragma unroll
                for (int kc = 0; kc < 2; kc++) {
                    uint32_t off = SWZ128((uint32_t)((mb * 8 + rowk) * 128 + kc * 64) + cbk);
                    uint32_t k0, k1, k2, k3;
                    LDSM_X4(k0, k1, k2, k3, kh_b + off);
                    MMA16816(c0,c1,c2,c3, QH[2*kc][0],QH[2*kc][1],QH[2*kc][2],QH[2*kc][3], k0,k1);
                    MMA16816(c0,c1,c2,c3, QH[2*kc+1][0],QH[2*kc+1][1],QH[2*kc+1][2],QH[2*kc+1][3], k2,k3);
                    MMA16816(c0,c1,c2,c3, QL[2*kc][0],QL[2*kc][1],QL[2*kc][2],QL[2*kc][3], k0,k1);
                    MMA16816(c0,c1,c2,c3, QL[2*kc+1][0],QL[2*kc+1][1],QL[2*kc+1][2],QL[2*kc+1][3], k2,k3);
                    LDSM_X4(k0, k1, k2, k3, kl_b + off);
                    MMA16816(c0,c1,c2,c3, QH[2*kc][0],QH[2*kc][1],QH[2*kc][2],QH[2*kc][3], k0,k1);
                    MMA16816(c0,c1,c2,c3, QH[2*kc+1][0],QH[2*kc+1][1],QH[2*kc+1][2],QH[2*kc+1][3], k2,k3);
                }
                float p0 = ex2f(c0), p1 = ex2f(c1), p2 = ex2f(c2), p3 = ex2f(c3);
                Lg  += p0 + p1;
                Lg8 += p2 + p3;
                uint32_t h01 = pack_bf16(p0, p1);
                uint32_t h23 = pack_bf16(p2, p3);
                float l0 = p0 - __uint_as_float(h01 << 16);
                float l1 = p1 - __uint_as_float(h01 & 0xFFFF0000u);
                float l2 = p2 - __uint_as_float(h23 << 16);
                float l3 = p3 - __uint_as_float(h23 & 0xFFFF0000u);
                PH2[half][0] = h01; PH2[half][1] = h23;
                PL2[half][0] = pack_bf16(l0, l1); PL2[half][1] = pack_bf16(l2, l3);
            }

            uint32_t a0 = PH2[0][0], a1 = PH2[0][1], a2 = PH2[1][0], a3 = PH2[1][1];
            uint32_t e0 = PL2[0][0], e1 = PL2[0][1], e2 = PL2[1][0], e3 = PL2[1][1];
#pragma unroll
            for (int oc = 0; oc < 4; oc++) {
                uint32_t off = SWZ128((uint32_t)((mbp * 16 + rv) * 128 + oc * 32) + cbv);
                uint32_t v0, v1, v2, v3;
                LDSM_X4T(v0, v1, v2, v3, vh_b + off);
                MMA16816(Oa[2*oc][0],Oa[2*oc][1],Oa[2*oc][2],Oa[2*oc][3], a0,a1,a2,a3, v0,v1);
                MMA16816(Oa[2*oc+1][0],Oa[2*oc+1][1],Oa[2*oc+1][2],Oa[2*oc+1][3], a0,a1,a2,a3, v2,v3);
                MMA16816(Oa[2*oc][0],Oa[2*oc][1],Oa[2*oc][2],Oa[2*oc][3], e0,e1,e2,e3, v0,v1);
                MMA16816(Oa[2*oc+1][0],Oa[2*oc+1][1],Oa[2*oc+1][2],Oa[2*oc+1][3], e0,e1,e2,e3, v2,v3);
                LDSM_X4T(v0, v1, v2, v3, vl_b + off);
                MMA16816(Oa[2*oc][0],Oa[2*oc][1],Oa[2*oc][2],Oa[2*oc][3], a0,a1,a2,a3, v0,v1);
                MMA16816(Oa[2*oc+1][0],Oa[2*oc+1][1],Oa[2*oc+1][2],Oa[2*oc+1][3], a0,a1,a2,a3, v2,v3);
            }
        }
        __syncthreads();
    }

    // ---- epilogue: normalize O, stage bf16 hi/lo [64 o][64 n] into S0 ----
    Lg  += __shfl_xor_sync(0xffffffffu, Lg, 1);
    Lg  += __shfl_xor_sync(0xffffffffu, Lg, 2);
    Lg8 += __shfl_xor_sync(0xffffffffu, Lg8, 1);
    Lg8 += __shfl_xor_sync(0xffffffffu, Lg8, 2);
    float invg = 1.f / Lg, invg8 = 1.f / Lg8;

    int g = lane >> 2, u = lane & 3;
    int rA = r0 + g, rB = r0 + 8 + g;
#pragma unroll
    for (int ob = 0; ob < 8; ob++) {
        int o0 = ob * 8 + 2 * u;
#pragma unroll
        for (int q = 0; q < 2; q++) {
            float vA = Oa[ob][q] * invg;       // (rA, o0+q)
            float vB = Oa[ob][2 + q] * invg8;  // (rB, o0+q)
            __nv_bfloat16 hA = __float2bfloat16(vA);
            __nv_bfloat16 hB = __float2bfloat16(vB);
            uint32_t offA = SWZ128((uint32_t)((o0 + q) * 128 + rA * 2));
            uint32_t offB = SWZ128((uint32_t)((o0 + q) * 128 + rB * 2));
            *(__nv_bfloat16*)(smem + S0 + offA) = hA;
            *(__nv_bfloat16*)(smem + S0 + offB) = hB;
            *(__nv_bfloat16*)(smem + S0 + 8192 + offA) =
                __float2bfloat16(vA - __bfloat162float(hA));
            *(__nv_bfloat16*)(smem + S0 + 8192 + offB) =
                __float2bfloat16(vB - __bfloat162float(hB));
        }
    }
    __syncthreads();

    // ---- y = wc @ O via 3-split MMAs; warp owns c rows [wid*32, wid*32+32) --
    float Ya[2][8][4];
#pragma unroll
    for (int i = 0; i < 2; i++)
#pragma unroll
        for (int j = 0; j < 8; j++)
#pragma unroll
            for (int k = 0; k < 4; k++) Ya[i][j][k] = 0.f;

    {
        int arow = wid * 32 + (lane & 7) + ((lane >> 3) & 1) * 8;
        uint32_t acq = ((lane >> 4) & 1) * 16;
#pragma unroll
        for (int rb = 0; rb < 2; rb++) {
#pragma unroll
            for (int k = 0; k < 4; k++) {
                uint32_t aoff = SWZ128((uint32_t)((arow + rb * 16) * 128 + k * 32) + acq);
                uint32_t ah0, ah1, ah2, ah3, al0, al1, al2, al3;
                LDSM_X4(ah0, ah1, ah2, ah3, sb + WCC + aoff);
                LDSM_X4(al0, al1, al2, al3, sb + WCC + 16384 + aoff);
#pragma unroll
                for (int oc = 0; oc < 4; oc++) {
                    uint32_t boff = SWZ128((uint32_t)((k * 16 + rv) * 128 + oc * 32) + cbv);
                    uint32_t b0, b1, b2, b3;
                    LDSM_X4T(b0, b1, b2, b3, sb + S0 + boff);
                    MMA16816(Ya[rb][2*oc][0],Ya[rb][2*oc][1],Ya[rb][2*oc][2],Ya[rb][2*oc][3],
                             ah0,ah1,ah2,ah3, b0,b1);
                    MMA16816(Ya[rb][2*oc+1][0],Ya[rb][2*oc+1][1],Ya[rb][2*oc+1][2],Ya[rb][2*oc+1][3],
                             ah0,ah1,ah2,ah3, b2,b3);
                    MMA16816(Ya[rb][2*oc][0],Ya[rb][2*oc][1],Ya[rb][2*oc][2],Ya[rb][2*oc][3],
                             al0,al1,al2,al3, b0,b1);
                    MMA16816(Ya[rb][2*oc+1][0],Ya[rb][2*oc+1][1],Ya[rb][2*oc+1][2],Ya[rb][2*oc+1][3],
                             al0,al1,al2,al3, b2,b3);
                    LDSM_X4T(b0, b1, b2, b3, sb + S0 + 8192 + boff);
                    MMA16816(Ya[rb][2*oc][0],Ya[rb][2*oc][1],Ya[rb][2*oc][2],Ya[rb][2*oc][3],
                             ah0,ah1,ah2,ah3, b0,b1);
                    MMA16816(Ya[rb][2*oc+1][0],Ya[rb][2*oc+1][1],Ya[rb][2*oc+1][2],Ya[rb][2*oc+1][3],
                             ah0,ah1,ah2,ah3, b2,b3);
                }
            }
        }
    }

    // ---- BN + ReLU + residual + store ----
#pragma unroll
    for (int rb = 0; rb < 2; rb++) {
        int c0 = wid * 32 + rb * 16 + g;
        int c1 = c0 + 8;
        float iv0 = __ldg(gam + c0) * rsqrtf(__ldg(va + c0) + 1e-5f);
        float iv1 = __ldg(gam + c1) * rsqrtf(__ldg(va + c1) + 1e-5f);
        float sh0 = __ldg(bet + c0) - __ldg(mea + c0) * iv0;
        float sh1 = __ldg(bet + c1) - __ldg(mea + c1) * iv1;
        float bb0 = __ldg(bc + c0), bb1 = __ldg(bc + c1);
        size_t base0 = (size_t)b * CC * NN + (size_t)c0 * NN + n0;
        size_t base1 = (size_t)b * CC * NN + (size_t)c1 * NN + n0;
#pragma unroll
        for (int nb = 0; nb < 8; nb++) {
            int n = nb * 8 + 2 * u;
            float2 i0 = *(const float2*)&img[base0 + n];
            float2 i1 = *(const float2*)&img[base1 + n];
            float y;
            float2 o0v, o1v;
            y = (Ya[rb][nb][0] + bb0) * iv0 + sh0; o0v.x = i0.x + fmaxf(y, 0.f);
            y = (Ya[rb][nb][1] + bb0) * iv0 + sh0; o0v.y = i0.y + fmaxf(y, 0.f);
            y = (Ya[rb][nb][2] + bb1) * iv1 + sh1; o1v.x = i1.x + fmaxf(y, 0.f);
            y = (Ya[rb][nb][3] + bb1) * iv1 + sh1; o1v.y = i1.y + fmaxf(y, 0.f);
            *(float2*)&out[base0 + n] = o0v;
            *(float2*)&out[base1 + n] = o1v;
        }
    }
}

// ---------------------------------------------------------------------------
extern "C" void kernel_launch(void* const* d_in, const int* in_sizes, int n_in,
                              void* d_out, int out_size)
{
    const float* range_x = (const float*)d_in[0];
    const float* img     = (const float*)d_in[1];
    const float* wq      = (const float*)d_in[2];
    const float* bq      = (const float*)d_in[3];
    const float* wk      = (const float*)d_in[4];
    const float* bk      = (const float*)d_in[5];
    const float* wv      = (const float*)d_in[6];
    const float* bv      = (const float*)d_in[7];
    const float* wc      = (const float*)d_in[8];
    const float* bc      = (const float*)d_in[9];
    const float* g       = (const float*)d_in[10];
    const float* be      = (const float*)d_in[11];
    const float* mn      = (const float*)d_in[12];
    const float* vr      = (const float*)d_in[13];
    float* out = (float*)d_out;

    __nv_bfloat16 *kh, *kl, *vh, *vl;
    cudaGetSymbolAddress((void**)&kh, KhG);
    cudaGetSymbolAddress((void**)&kl, KlG);
    cudaGetSymbolAddress((void**)&vh, VhG);
    cudaGetSymbolAddress((void**)&vl, VlG);

    int smProj = 20480 * sizeof(float);   // 80KB

    cudaFuncSetAttribute(proj2_kernel, cudaFuncAttributeMaxDynamicSharedMemorySize, smProj);
    cudaFuncSetAttribute(attn_fused_kernel, cudaFuncAttributeMaxDynamicSharedMemorySize, SMEM_ATTN);

    dim3 gp(NN / 64, BB);   // 64 x 4 = 256 CTAs

    proj2_kernel<<<gp, 256, smProj>>>(img, wk, bk, kh, kl, wv, bv, vh, vl);
    attn_fused_kernel<<<gp, 128, SMEM_ATTN>>>(range_x, wq, bq, wc, bc,
                                              g, be, mn, vr, img, out);
}